// round 8
// baseline (speedup 1.0000x reference)
#include <cuda_runtime.h>
#include <math.h>

// Problem constants (fixed by the dataset): B=8192 rows, H=4096 hidden, E=8 experts, TOP_K=2.
#define B_ROWS 8192
#define HDIM   4096
#define NEXP   8

// Per-row gating result: {p_top1, p_top2, bits(idx_top1), bits(idx_top2)}
__device__ float4 g_rowgate[B_ROWS];

// Packed f32x2 helpers (sm_10x has a packed fp32 pipe; only reachable via PTX)
#define FMA2(d, a, b, c) asm("fma.rn.f32x2 %0, %1, %2, %3;" : "=l"(d) : "l"(a), "l"(b), "l"(c))
#define ADD2(d, a, b)    asm("add.rn.f32x2 %0, %1, %2;"     : "=l"(d) : "l"(a), "l"(b))
#define PACK2(d, x)      asm("mov.b64 %0, {%1, %1};"        : "=l"(d) : "r"(x))
#define UNPK2(lo, hi, s) asm("mov.b64 {%0, %1}, %2;"        : "=r"(lo), "=r"(hi) : "l"(s))

// ---------------------------------------------------------------------------
// Kernel 1: gating. grid = #SMs, block = 1024 threads.
// Thread t owns h = 4t..4t+3 for ALL rows -> its 32 gate weights live in
// registers (16 packed f32x2), loaded exactly once. Per row: one float4
// hidden load (prefetched one row ahead), 16 packed FMAs into 4 packed
// accumulators, then a distribute-reduce:
//   levels xor1/xor2 shrink 4 packed accs -> 1 packed (experts spread over
//   lane bits 0..1), level xor4 unpacks (bit 2), xor8/xor16 finish the warp.
//   Lane l ends holding expert e = bitrev3(l) summed over the warp.
// Cross-warp: 32x8 partials in smem (pad 9 -> conflict-free), warp w<8 sums
// expert w, thread 0 does top-2 + two-way softmax (== softmax+topk+renorm).
// ---------------------------------------------------------------------------
__global__ __launch_bounds__(1024, 1) void gate_kernel(
    const float* __restrict__ hidden,
    const float* __restrict__ gw,     // (H, E) row-major
    const float* __restrict__ gb)     // (E,)
{
    const int t    = threadIdx.x;
    const int lane = t & 31;
    const int wid  = t >> 5;

    // Gate weights for h = 4t..4t+3: 32 contiguous floats = 16 f32x2 pairs.
    long long g2[16];
    const long long* gwp = reinterpret_cast<const long long*>(gw) + (size_t)t * 16;
#pragma unroll
    for (int i = 0; i < 16; i++) g2[i] = gwp[i];

    __shared__ float s_part[32 * 9];
    __shared__ float s_scores[8];

    // expert index held by this lane after the distribute-reduce: bitrev3(lane)
    const int e_lane = ((lane & 1) << 2) | (lane & 2) | ((lane >> 2) & 1);

    const float4* hv = reinterpret_cast<const float4*>(hidden);

    int row = (int)blockIdx.x;
    float4 v = hv[(size_t)row * (HDIM / 4) + t];

    for (; row < B_ROWS; row += gridDim.x) {
        // Prefetch next row before the compute/reduce phase.
        const int nrow = row + gridDim.x;
        float4 vn = v;
        if (nrow < B_ROWS) vn = hv[(size_t)nrow * (HDIM / 4) + t];

        // acc_j holds experts {2j, 2j+1} packed. 0LL == {0.0f, 0.0f}.
        long long acc0 = 0, acc1 = 0, acc2 = 0, acc3 = 0;
        const float vk[4] = {v.x, v.y, v.z, v.w};
#pragma unroll
        for (int k = 0; k < 4; k++) {
            long long pv;
            PACK2(pv, __float_as_int(vk[k]));
            FMA2(acc0, pv, g2[k * 4 + 0], acc0);
            FMA2(acc1, pv, g2[k * 4 + 1], acc1);
            FMA2(acc2, pv, g2[k * 4 + 2], acc2);
            FMA2(acc3, pv, g2[k * 4 + 3], acc3);
        }

        // --- distribute-reduce: 8 values x 32 lanes -> 1 value/lane in 9 shfl-equivalents ---
        {   // level 0: xor 1. lo lanes keep experts 0-3, hi lanes keep 4-7.
            const bool hi = lane & 1;
            long long s0 = hi ? acc0 : acc2;
            long long s1 = hi ? acc1 : acc3;
            long long r0 = __shfl_xor_sync(0xffffffffu, s0, 1);
            long long r1 = __shfl_xor_sync(0xffffffffu, s1, 1);
            long long k0 = hi ? acc2 : acc0;
            long long k1 = hi ? acc3 : acc1;
            ADD2(acc0, k0, r0);
            ADD2(acc1, k1, r1);
        }
        {   // level 1: xor 2. keep one packed pair.
            const bool hi = lane & 2;
            long long s0 = hi ? acc0 : acc1;
            long long r0 = __shfl_xor_sync(0xffffffffu, s0, 2);
            long long k0 = hi ? acc1 : acc0;
            ADD2(acc0, k0, r0);
        }
        float val;
        {   // level 2: xor 4, unpack the pair.
            int lo_i, hi_i;
            UNPK2(lo_i, hi_i, acc0);
            const float f0 = __int_as_float(lo_i);
            const float f1 = __int_as_float(hi_i);
            const bool hi = lane & 4;
            const float s = hi ? f0 : f1;
            const float r = __shfl_xor_sync(0xffffffffu, s, 4);
            val = (hi ? f1 : f0) + r;
        }
        val += __shfl_xor_sync(0xffffffffu, val, 8);
        val += __shfl_xor_sync(0xffffffffu, val, 16);

        if (lane < 8) s_part[wid * 9 + e_lane] = val;
        __syncthreads();

        if (t < 256) {
            const int w = t >> 5;                 // warp w (<8) reduces expert w
            float p = s_part[lane * 9 + w];       // pad-9: conflict-free
            p += __shfl_xor_sync(0xffffffffu, p, 16);
            p += __shfl_xor_sync(0xffffffffu, p, 8);
            p += __shfl_xor_sync(0xffffffffu, p, 4);
            p += __shfl_xor_sync(0xffffffffu, p, 2);
            p += __shfl_xor_sync(0xffffffffu, p, 1);
            if (lane == 0) s_scores[w] = p + gb[w];
        }
        __syncthreads();

        if (t == 0) {
            float s[8];
#pragma unroll
            for (int e = 0; e < 8; e++) s[e] = s_scores[e];
            // top-2, strict '>' keeps earliest index on ties (matches lax.top_k)
            int i1 = 0; float b1 = s[0];
#pragma unroll
            for (int e = 1; e < 8; e++) if (s[e] > b1) { b1 = s[e]; i1 = e; }
            int i2 = -1; float b2 = -3.402823466e38f;
#pragma unroll
            for (int e = 0; e < 8; e++) if (e != i1 && s[e] > b2) { b2 = s[e]; i2 = e; }
            // softmax over all 8 then renorm over top-2 == 2-way softmax:
            const float p1 = 1.0f / (1.0f + expf(b2 - b1));
            const float p2 = 1.0f - p1;
            g_rowgate[row] = make_float4(p1, p2, __int_as_float(i1), __int_as_float(i2));
        }

        v = vn;
    }
}

// ---------------------------------------------------------------------------
// Kernel 2: combine. One block per row, 256 threads, float4 streams.
// out[b,:] = p0 * eo[i0, b, :] + p1 * eo[i1, b, :]
// 8 float4 loads in flight per thread before any math -> DRAM-bound.
// ---------------------------------------------------------------------------
__global__ __launch_bounds__(256) void combine_kernel(
    const float* __restrict__ eo,
    float* __restrict__ out)
{
    const int b = (int)blockIdx.x;
    const float4 rg = g_rowgate[b];           // broadcast load
    const float p0 = rg.x, p1 = rg.y;
    const int i0 = __float_as_int(rg.z);
    const int i1 = __float_as_int(rg.w);

    const float4* e0 = reinterpret_cast<const float4*>(eo + ((size_t)i0 * B_ROWS + b) * HDIM);
    const float4* e1 = reinterpret_cast<const float4*>(eo + ((size_t)i1 * B_ROWS + b) * HDIM);
    float4* o = reinterpret_cast<float4*>(out + (size_t)b * HDIM);

    const int t = threadIdx.x;
    float4 a[4], c[4];
#pragma unroll
    for (int k = 0; k < 4; k++) {
        a[k] = e0[t + k * 256];
        c[k] = e1[t + k * 256];
    }
#pragma unroll
    for (int k = 0; k < 4; k++) {
        float4 r;
        r.x = p0 * a[k].x + p1 * c[k].x;
        r.y = p0 * a[k].y + p1 * c[k].y;
        r.z = p0 * a[k].z + p1 * c[k].z;
        r.w = p0 * a[k].w + p1 * c[k].w;
        o[t + k * 256] = r;
    }
}

// ---------------------------------------------------------------------------
// Launch. Inputs (metadata order): hidden_states (B,H) f32, expert_outputs
// (E,B,H) f32, gate_w (H,E) f32, gate_b (E,) f32. Output: (B,H) f32.
// Graph-capturable: two kernel launches on stream 0, no allocs, no syncs.
// ---------------------------------------------------------------------------
extern "C" void kernel_launch(void* const* d_in, const int* in_sizes, int n_in,
                              void* d_out, int out_size)
{
    const float* hidden = (const float*)d_in[0];
    const float* eo     = (const float*)d_in[1];
    const float* gw     = (const float*)d_in[2];
    const float* gb     = (const float*)d_in[3];
    float* out = (float*)d_out;

    gate_kernel<<<152, 1024>>>(hidden, gw, gb);
    combine_kernel<<<B_ROWS, 256>>>(eo, out);
}

// round 9
// speedup vs baseline: 1.0137x; 1.0137x over previous
#include <cuda_runtime.h>
#include <math.h>

// Problem constants: B=8192 rows, H=4096 hidden, E=8 experts, TOP_K=2. fp32.
#define B_ROWS 8192
#define HDIM   4096
#define NEXP   8
#define RSTEP  152   // row-group stride (gate grid = 2*RSTEP blocks)

// Partial gate scores: g_part[row*16 + half*8 + e]  (half = which H-2048 slice)
__device__ float g_part[(size_t)B_ROWS * 16];

// Packed f32x2 helpers (sm_10x packed fp32 pipe, PTX-only)
#define FMA2(d, a, b, c) asm("fma.rn.f32x2 %0, %1, %2, %3;" : "=l"(d) : "l"(a), "l"(b), "l"(c))
#define ADD2(d, a, b)    asm("add.rn.f32x2 %0, %1, %2;"     : "=l"(d) : "l"(a), "l"(b))
#define PACK2(d, x)      asm("mov.b64 %0, {%1, %1};"        : "=l"(d) : "r"(x))
#define UNPK2(lo, hi, s) asm("mov.b64 {%0, %1}, %2;"        : "=r"(lo), "=r"(hi) : "l"(s))

// ---------------------------------------------------------------------------
// Kernel 1: gate partials. grid = 2*RSTEP blocks x 512 threads, 2 blocks/SM.
// Block pair (2g, 2g+1) splits H: half = bid&1 owns h in [half*2048, +2048).
// Thread t owns h = half*2048 + 4t..+3 for ALL its rows -> its 32 gate
// weights stay in registers (16 packed f32x2), loaded once. Depth-2 hidden
// prefetch per thread (x2 blocks/SM = 64KB/SM in flight, above Little's-law
// ~29KB). Per row: 16 packed FMAs, 9-shfl distribute-reduce (lane l ends
// holding expert bitrev3(l) summed over warp), cross-warp smem reduce
// (pad-9, conflict-free), 8 partial scores -> g_part. Top-2 happens later
// in the combine kernel.
// ---------------------------------------------------------------------------
__global__ __launch_bounds__(512, 2) void gate_kernel(
    const float* __restrict__ hidden,
    const float* __restrict__ gw)     // (H, E) row-major
{
    const int t    = threadIdx.x;
    const int lane = t & 31;
    const int wid  = t >> 5;
    const int half = (int)blockIdx.x & 1;
    const int r0   = (int)blockIdx.x >> 1;   // 0..RSTEP-1

    // 32 contiguous gate weights for this thread's 4 h positions.
    long long g2[16];
    const long long* gwp =
        reinterpret_cast<const long long*>(gw) + ((size_t)half * 512 + t) * 16;
#pragma unroll
    for (int i = 0; i < 16; i++) g2[i] = gwp[i];

    __shared__ float s_part[16 * 9];

    // expert index held by this lane after the distribute-reduce: bitrev3(lane)
    const int e_lane = ((lane & 1) << 2) | (lane & 2) | ((lane >> 2) & 1);

    const float4* hv =
        reinterpret_cast<const float4*>(hidden) + (size_t)half * 512 + t;

    // depth-2 rolling prefetch (both initial rows are always in range:
    // r0 <= 151, r0+RSTEP <= 303 < 8192)
    float4 buf0 = hv[(size_t)r0 * (HDIM / 4)];
    float4 buf1 = hv[(size_t)(r0 + RSTEP) * (HDIM / 4)];

    auto process = [&](float4 v, int row) {
        // acc_j holds experts {2j, 2j+1} packed. 0LL == {0.0f, 0.0f}.
        long long acc0 = 0, acc1 = 0, acc2 = 0, acc3 = 0;
        const float vk[4] = {v.x, v.y, v.z, v.w};
#pragma unroll
        for (int k = 0; k < 4; k++) {
            long long pv;
            PACK2(pv, __float_as_int(vk[k]));
            FMA2(acc0, pv, g2[k * 4 + 0], acc0);
            FMA2(acc1, pv, g2[k * 4 + 1], acc1);
            FMA2(acc2, pv, g2[k * 4 + 2], acc2);
            FMA2(acc3, pv, g2[k * 4 + 3], acc3);
        }
        {   // level 0: xor 1
            const bool hi = lane & 1;
            long long s0 = hi ? acc0 : acc2;
            long long s1 = hi ? acc1 : acc3;
            long long q0 = __shfl_xor_sync(0xffffffffu, s0, 1);
            long long q1 = __shfl_xor_sync(0xffffffffu, s1, 1);
            long long k0 = hi ? acc2 : acc0;
            long long k1 = hi ? acc3 : acc1;
            ADD2(acc0, k0, q0);
            ADD2(acc1, k1, q1);
        }
        {   // level 1: xor 2
            const bool hi = lane & 2;
            long long s0 = hi ? acc0 : acc1;
            long long q0 = __shfl_xor_sync(0xffffffffu, s0, 2);
            long long k0 = hi ? acc1 : acc0;
            ADD2(acc0, k0, q0);
        }
        float val;
        {   // level 2: xor 4, unpack
            int lo_i, hi_i;
            UNPK2(lo_i, hi_i, acc0);
            const float f0 = __int_as_float(lo_i);
            const float f1 = __int_as_float(hi_i);
            const bool hi = lane & 4;
            const float s = hi ? f0 : f1;
            const float q = __shfl_xor_sync(0xffffffffu, s, 4);
            val = (hi ? f1 : f0) + q;
        }
        val += __shfl_xor_sync(0xffffffffu, val, 8);
        val += __shfl_xor_sync(0xffffffffu, val, 16);

        if (lane < 8) s_part[wid * 9 + e_lane] = val;
        __syncthreads();

        if (t < 256) {
            const int w = t >> 5;                           // warp w reduces expert w
            float p = (lane < 16) ? s_part[lane * 9 + w] : 0.0f;
            p += __shfl_xor_sync(0xffffffffu, p, 8);
            p += __shfl_xor_sync(0xffffffffu, p, 4);
            p += __shfl_xor_sync(0xffffffffu, p, 2);
            p += __shfl_xor_sync(0xffffffffu, p, 1);
            if (lane == 0) g_part[(size_t)row * 16 + half * 8 + w] = p;
        }
        __syncthreads();   // s_part reused next row
    };

    for (int r = r0; r < B_ROWS; r += 2 * RSTEP) {
        {
            float4 v = buf0;
            const int rp = r + 2 * RSTEP;
            if (rp < B_ROWS) buf0 = hv[(size_t)rp * (HDIM / 4)];
            process(v, r);
        }
        if (r + RSTEP < B_ROWS) {   // uniform guard -> barrier-safe
            float4 v = buf1;
            const int rp = r + 3 * RSTEP;
            if (rp < B_ROWS) buf1 = hv[(size_t)rp * (HDIM / 4)];
            process(v, r + RSTEP);
        }
    }
}

// ---------------------------------------------------------------------------
// Kernel 2: finalize top-2 + combine. One block per row, 256 threads.
// Warp 0 preamble: score[e] = part[half0] + part[half1] + bias, then two
// shfl max-reduce passes with smallest-index tie-break (matches lax.top_k),
// 2-way softmax (== softmax + top-2 renorm). Then the streaming combine:
// out[b,:] = p0 * eo[i0,b,:] + p1 * eo[i1,b,:], float4, 8 loads in flight
// per thread, .cs (streaming) hints — no reuse, don't pollute L2.
// ---------------------------------------------------------------------------
__global__ __launch_bounds__(256) void combine_kernel(
    const float* __restrict__ eo,
    const float* __restrict__ gb,
    float* __restrict__ out)
{
    const int b = (int)blockIdx.x;
    __shared__ float4 bc;

    if (threadIdx.x < 32) {
        const int lane = threadIdx.x;
        float s = -3.402823466e38f;
        if (lane < 8)
            s = g_part[(size_t)b * 16 + lane] + g_part[(size_t)b * 16 + 8 + lane]
                + gb[lane];

        float v1 = s; int i1 = lane;
#pragma unroll
        for (int off = 4; off; off >>= 1) {
            const float ov = __shfl_xor_sync(0xffffffffu, v1, off);
            const int   oi = __shfl_xor_sync(0xffffffffu, i1, off);
            if (ov > v1 || (ov == v1 && oi < i1)) { v1 = ov; i1 = oi; }
        }
        // lanes 0..7 all hold (v1, i1) now
        float v2 = (lane == i1) ? -3.402823466e38f : s;
        int i2 = lane;
#pragma unroll
        for (int off = 4; off; off >>= 1) {
            const float ov = __shfl_xor_sync(0xffffffffu, v2, off);
            const int   oi = __shfl_xor_sync(0xffffffffu, i2, off);
            if (ov > v2 || (ov == v2 && oi < i2)) { v2 = ov; i2 = oi; }
        }
        if (lane == 0) {
            // softmax over 8 then renorm over top-2 == 2-way softmax
            const float p1 = 1.0f / (1.0f + expf(v2 - v1));
            bc = make_float4(p1, 1.0f - p1, __int_as_float(i1), __int_as_float(i2));
        }
    }
    __syncthreads();

    const float4 rg = bc;
    const float p0 = rg.x, p1 = rg.y;
    const int i0 = __float_as_int(rg.z);
    const int i1 = __float_as_int(rg.w);

    const float4* e0 =
        reinterpret_cast<const float4*>(eo + ((size_t)i0 * B_ROWS + b) * HDIM);
    const float4* e1 =
        reinterpret_cast<const float4*>(eo + ((size_t)i1 * B_ROWS + b) * HDIM);
    float4* o = reinterpret_cast<float4*>(out + (size_t)b * HDIM);

    const int t = threadIdx.x;
    float4 a[4], c[4];
#pragma unroll
    for (int k = 0; k < 4; k++) {
        a[k] = __ldcs(&e0[t + k * 256]);
        c[k] = __ldcs(&e1[t + k * 256]);
    }
#pragma unroll
    for (int k = 0; k < 4; k++) {
        float4 r;
        r.x = p0 * a[k].x + p1 * c[k].x;
        r.y = p0 * a[k].y + p1 * c[k].y;
        r.z = p0 * a[k].z + p1 * c[k].z;
        r.w = p0 * a[k].w + p1 * c[k].w;
        __stcs(&o[t + k * 256], r);
    }
}

// ---------------------------------------------------------------------------
// Launch. Inputs (metadata order): hidden_states (B,H) f32, expert_outputs
// (E,B,H) f32, gate_w (H,E) f32, gate_b (E,) f32. Output: (B,H) f32.
// Graph-capturable: two kernel launches on stream 0, no allocs, no syncs.
// ---------------------------------------------------------------------------
extern "C" void kernel_launch(void* const* d_in, const int* in_sizes, int n_in,
                              void* d_out, int out_size)
{
    const float* hidden = (const float*)d_in[0];
    const float* eo     = (const float*)d_in[1];
    const float* gw     = (const float*)d_in[2];
    const float* gb     = (const float*)d_in[3];
    float* out = (float*)d_out;

    gate_kernel<<<2 * RSTEP, 512>>>(hidden, gw);
    combine_kernel<<<B_ROWS, 256>>>(eo, gb, out);
}